// round 1
// baseline (speedup 1.0000x reference)
#include <cuda_runtime.h>
#include <cstdint>

#define B_ROWS 65536
#define C_COLS 1024
#define D_DIM  64
#define BM     32
#define THREADS 512

__device__ float  g_wn2[C_COLS];
__device__ double g_loss;

// ---------------------------------------------------------------------------
// Kernel 1: codebook row norms + zero loss accumulator (re-run every replay)
// ---------------------------------------------------------------------------
__global__ void vq_precompute(const float* __restrict__ cb) {
    int c = threadIdx.x;
    if (c == 0) g_loss = 0.0;
    if (c < C_COLS) {
        const float4* row = (const float4*)(cb + (size_t)c * D_DIM);
        float s = 0.f;
#pragma unroll
        for (int i = 0; i < 16; i++) {
            float4 v = row[i];
            s += v.x * v.x + v.y * v.y + v.z * v.z + v.w * v.w;
        }
        g_wn2[c] = s;
    }
}

// monotonic float->uint mapping (total order, preserves <)
__device__ __forceinline__ unsigned int ordered_u32(float f) {
    unsigned int u = __float_as_uint(f);
    return (u & 0x80000000u) ? ~u : (u | 0x80000000u);
}

// ---------------------------------------------------------------------------
// Kernel 2: fused GEMM + softassign + argmax + gather + loss partials.
// Block: 32 rows x all 1024 cols. 512 threads = 8 ty-groups (4 rows each)
// x 64 tx-groups (8 cols each). Codebook staged k-major in 2 tiles of 512 cols.
// ---------------------------------------------------------------------------
__global__ void __launch_bounds__(THREADS, 1)
vq_main(const float* __restrict__ z, const float* __restrict__ cb,
        float* __restrict__ q_out, float* __restrict__ zq_out) {
    extern __shared__ float smem[];
    float* z_s   = smem;                      // 32*64      = 2048 f
    float* cb_s  = smem + 2048;               // 64*512     = 32768 f (k-major)
    float* wn_s  = smem + 2048 + 32768;       // 1024 f
    float* zn2_s = wn_s + 1024;               // 32 f
    float* inv_s = zn2_s + 32;                // 32 f
    unsigned int* bc_s = (unsigned int*)(inv_s + 32);  // 32 u32
    // aliased onto cb_s AFTER both tiles are consumed:
    float* part_sum = cb_s;                                    // 32*64 f
    unsigned long long* part_key = (unsigned long long*)(cb_s + 2048); // 32*64 u64

    const int t  = threadIdx.x;
    const int ty = t >> 6;   // 0..7  -> rows 4*ty .. 4*ty+3
    const int tx = t & 63;   // 0..63 -> cols 8*tx .. 8*tx+7 (per tile)
    const int r0 = blockIdx.x * BM;

    // stage wn2 and z tile
    wn_s[t]       = g_wn2[t];
    wn_s[t + 512] = g_wn2[t + 512];
    {
        int row = t >> 4, k4 = t & 15;
        ((float4*)z_s)[row * 16 + k4] =
            ((const float4*)(z + (size_t)(r0 + row) * D_DIM))[k4];
    }
    __syncthreads();
    if (t < 32) {
        float s = 0.f;
#pragma unroll
        for (int k = 0; k < 64; k++) { float v = z_s[t * 64 + k]; s += v * v; }
        zn2_s[t] = s;
    }

    float q_reg[64];
    float rs[4] = {0.f, 0.f, 0.f, 0.f};
    unsigned long long bkey[4] = {0ull, 0ull, 0ull, 0ull};

    const float4* zs4 = (const float4*)z_s;

#pragma unroll 1
    for (int tile = 0; tile < 2; tile++) {
        const int c0 = tile * 512;
        __syncthreads();   // previous-tile readers done before overwrite
        // load codebook tile transposed: cb_s[k][c-c0], thread t owns row c0+t
        {
            const float4* src = (const float4*)(cb + (size_t)(c0 + t) * D_DIM);
#pragma unroll
            for (int it = 0; it < 16; it++) {
                float4 v = src[it];
                int kk = it * 4;
                cb_s[(kk + 0) * 512 + t] = v.x;
                cb_s[(kk + 1) * 512 + t] = v.y;
                cb_s[(kk + 2) * 512 + t] = v.z;
                cb_s[(kk + 3) * 512 + t] = v.w;
            }
        }
        __syncthreads();

        float acc[4][8];
#pragma unroll
        for (int r = 0; r < 4; r++)
#pragma unroll
            for (int j = 0; j < 8; j++) acc[r][j] = 0.f;

        const float4* cs4 = (const float4*)cb_s;
#pragma unroll 4
        for (int k4 = 0; k4 < 16; k4++) {
            float zarr[4][4];
#pragma unroll
            for (int r = 0; r < 4; r++) {
                float4 zv = zs4[(4 * ty + r) * 16 + k4];
                zarr[r][0] = zv.x; zarr[r][1] = zv.y;
                zarr[r][2] = zv.z; zarr[r][3] = zv.w;
            }
#pragma unroll
            for (int i = 0; i < 4; i++) {
                int k = k4 * 4 + i;
                float4 a = cs4[k * 128 + tx * 2];
                float4 b = cs4[k * 128 + tx * 2 + 1];
                float cv[8] = {a.x, a.y, a.z, a.w, b.x, b.y, b.z, b.w};
#pragma unroll
                for (int r = 0; r < 4; r++)
#pragma unroll
                    for (int j = 0; j < 8; j++)
                        acc[r][j] = fmaf(zarr[r][i], cv[j], acc[r][j]);
            }
        }

        // epilogue per tile: d -> q_un, track rowsum + argmax(d)
#pragma unroll
        for (int r = 0; r < 4; r++) {
            int row = 4 * ty + r;
            float zn = zn2_s[row];
#pragma unroll
            for (int j = 0; j < 8; j++) {
                int c = c0 + tx * 8 + j;
                float d  = zn + wn_s[c] - 2.f * acc[r][j];
                float qv = 1.f / (1.f + d);
                q_reg[tile * 32 + r * 8 + j] = qv;
                rs[r] += qv;
                unsigned long long key =
                    ((unsigned long long)ordered_u32(d) << 32) |
                    (unsigned long long)(0xFFFFFFFFu - (unsigned int)c);
                if (key > bkey[r]) bkey[r] = key;
            }
        }
    }

    __syncthreads();  // cb_s free -> alias part arrays
#pragma unroll
    for (int r = 0; r < 4; r++) {
        int row = 4 * ty + r;
        part_sum[row * 64 + tx] = rs[r];
        part_key[row * 64 + tx] = bkey[r];
    }
    __syncthreads();
    if (t < 32) {
        float s = 0.f;
        unsigned long long bk = 0ull;
#pragma unroll 8
        for (int j = 0; j < 64; j++) {
            s += part_sum[t * 64 + j];
            unsigned long long k = part_key[t * 64 + j];
            if (k > bk) bk = k;
        }
        inv_s[t] = 1.f / s;
        bc_s[t]  = 0xFFFFFFFFu - (unsigned int)(bk & 0xFFFFFFFFull);
    }
    __syncthreads();

    // write normalized q
#pragma unroll
    for (int tile = 0; tile < 2; tile++) {
#pragma unroll
        for (int r = 0; r < 4; r++) {
            int row = 4 * ty + r;
            float inv = inv_s[row];
            float* dst = q_out + (size_t)(r0 + row) * C_COLS + tile * 512 + tx * 8;
            float4 o0, o1;
            o0.x = q_reg[tile * 32 + r * 8 + 0] * inv;
            o0.y = q_reg[tile * 32 + r * 8 + 1] * inv;
            o0.z = q_reg[tile * 32 + r * 8 + 2] * inv;
            o0.w = q_reg[tile * 32 + r * 8 + 3] * inv;
            o1.x = q_reg[tile * 32 + r * 8 + 4] * inv;
            o1.y = q_reg[tile * 32 + r * 8 + 5] * inv;
            o1.z = q_reg[tile * 32 + r * 8 + 6] * inv;
            o1.w = q_reg[tile * 32 + r * 8 + 7] * inv;
            ((float4*)dst)[0] = o0;
            ((float4*)dst)[1] = o1;
        }
    }

    // gather z_q = codebook[argmax] , write z_q_st, accumulate loss partial
    float lp;
    {
        int row = t >> 4, j4 = t & 15;
        unsigned int cbest = bc_s[row];
        float4 e  = ((const float4*)(cb + (size_t)cbest * D_DIM))[j4];
        float4 zv = ((const float4*)z_s)[row * 16 + j4];
        ((float4*)(zq_out + (size_t)(r0 + row) * D_DIM))[j4] = e;
        float dx = e.x - zv.x, dy = e.y - zv.y, dz = e.z - zv.z, dw = e.w - zv.w;
        lp = dx * dx + dy * dy + dz * dz + dw * dw;
    }
    part_sum[t] = lp;
    __syncthreads();
#pragma unroll
    for (int s = 256; s > 0; s >>= 1) {
        if (t < s) part_sum[t] += part_sum[t + s];
        __syncthreads();
    }
    if (t == 0) atomicAdd(&g_loss, (double)part_sum[0]);
}

// ---------------------------------------------------------------------------
// Kernel 3: finalize loss scalar
// ---------------------------------------------------------------------------
__global__ void vq_finalize(float* __restrict__ loss_out) {
    loss_out[0] = (float)(1.25 * g_loss / ((double)B_ROWS * (double)D_DIM));
}

extern "C" void kernel_launch(void* const* d_in, const int* in_sizes, int n_in,
                              void* d_out, int out_size) {
    (void)in_sizes; (void)n_in; (void)out_size;
    const float* z  = (const float*)d_in[0];
    const float* cb = (const float*)d_in[1];
    float* out = (float*)d_out;
    float* q_out    = out;                                           // [B,C]
    float* zq_out   = out + (size_t)B_ROWS * C_COLS;                 // [B,D]
    float* loss_out = out + (size_t)B_ROWS * C_COLS + (size_t)B_ROWS * D_DIM;

    size_t smem_bytes = (size_t)(2048 + 32768 + 1024 + 32 + 32 + 32) * 4;
    cudaFuncSetAttribute(vq_main, cudaFuncAttributeMaxDynamicSharedMemorySize,
                         (int)smem_bytes);

    vq_precompute<<<1, 1024>>>(cb);
    vq_main<<<B_ROWS / BM, THREADS, smem_bytes>>>(z, cb, q_out, zq_out);
    vq_finalize<<<1, 1>>>(loss_out);
}

// round 3
// speedup vs baseline: 2.5001x; 2.5001x over previous
#include <cuda_runtime.h>
#include <cstdint>

#define BM      32
#define THREADS 512
#define NWARP   16

__device__ float  g_bfrag[128 * 8 * 32 * 4];  // [ntg][kk][lane]{hi0,hi1,lo0,lo1}
__device__ float  g_wn1[1024];                // ||e_c||^2 + 1
__device__ double g_loss;

__device__ __forceinline__ uint32_t tf32_rna(float v) {
    uint32_t u; asm("cvt.rna.tf32.f32 %0, %1;" : "=r"(u) : "f"(v));
    return u;
}
__device__ __forceinline__ float rcpf(float x) {
    float r; asm("rcp.approx.f32 %0, %1;" : "=f"(r) : "f"(x)); return r;
}
__device__ __forceinline__ unsigned int ordered_u32(float f) {
    unsigned int u = __float_as_uint(f);
    return (u & 0x80000000u) ? ~u : (u | 0x80000000u);
}
__device__ __forceinline__ void mma_tf32(float* d, const uint32_t* a,
                                         uint32_t b0, uint32_t b1) {
    asm volatile(
        "mma.sync.aligned.m16n8k8.row.col.f32.tf32.tf32.f32 "
        "{%0,%1,%2,%3}, {%4,%5,%6,%7}, {%8,%9}, {%0,%1,%2,%3};"
        : "+f"(d[0]), "+f"(d[1]), "+f"(d[2]), "+f"(d[3])
        : "r"(a[0]), "r"(a[1]), "r"(a[2]), "r"(a[3]), "r"(b0), "r"(b1));
}

// ---------------------------------------------------------------------------
// Precompute 1: wn2+1, zero loss
// ---------------------------------------------------------------------------
__global__ void vq_norms(const float* __restrict__ cb) {
    int c = blockIdx.x * 128 + threadIdx.x;
    if (c == 0) g_loss = 0.0;
    if (c >= 1024) return;
    const float4* row = (const float4*)(cb + (size_t)c * 64);
    float s = 0.f;
#pragma unroll
    for (int i = 0; i < 16; i++) {
        float4 v = row[i];
        s += v.x * v.x + v.y * v.y + v.z * v.z + v.w * v.w;
    }
    g_wn1[c] = s + 1.f;
}

// ---------------------------------------------------------------------------
// Precompute 2: B fragments of (-2*codebook) in tf32 hi/lo, fragment order.
// B[k][n] with n = codebook row. Frag m16n8k8: b0=(k=tq, n=g), b1=(k=tq+4, n=g)
// ---------------------------------------------------------------------------
__global__ void vq_bfrag(const float* __restrict__ cb) {
    int idx  = blockIdx.x * 256 + threadIdx.x;   // 0..32767
    int lane = idx & 31;
    int kk   = (idx >> 5) & 7;
    int ntg  = idx >> 8;                         // 0..127
    int g = lane >> 2, tq = lane & 3;
    int c  = ntg * 8 + g;
    int k0 = kk * 8 + tq;
    float v0 = -2.f * cb[(size_t)c * 64 + k0];
    float v1 = -2.f * cb[(size_t)c * 64 + k0 + 4];
    uint32_t h0 = tf32_rna(v0), h1 = tf32_rna(v1);
    uint32_t l0 = tf32_rna(v0 - __uint_as_float(h0));
    uint32_t l1 = tf32_rna(v1 - __uint_as_float(h1));
    float4 o;
    o.x = __uint_as_float(h0); o.y = __uint_as_float(h1);
    o.z = __uint_as_float(l0); o.w = __uint_as_float(l1);
    ((float4*)g_bfrag)[idx] = o;
}

// ---------------------------------------------------------------------------
// Main fused kernel: 32 rows x 1024 cols per CTA, tf32x3 mma.sync GEMM
// ---------------------------------------------------------------------------
__global__ void __launch_bounds__(THREADS, 1)
vq_main(const float* __restrict__ z, const float* __restrict__ cb,
        float* __restrict__ q_out, float* __restrict__ zq_out) {
    __shared__ float z_s[32 * 64];        // raw z tile
    __shared__ float ahi_s[512 * 4];      // A hi frags [kk*2+mt][lane][4]
    __shared__ float alo_s[512 * 4];      // A lo frags
    __shared__ float wn_s[1024];
    __shared__ float zn2_s[32];
    __shared__ float inv_s[32];
    __shared__ int   bc_s[32];
    __shared__ float rs_p[NWARP][32];
    __shared__ unsigned long long key_p[NWARP][32];

    const int tid  = threadIdx.x;
    const int wid  = tid >> 5;
    const int lane = tid & 31;
    const int g    = lane >> 2;
    const int tq   = lane & 3;
    const int r0   = blockIdx.x * BM;

    // stage raw z (coalesced) + wn1
    ((float4*)z_s)[tid] = ((const float4*)(z + (size_t)r0 * 64))[tid];
    wn_s[tid]       = g_wn1[tid];
    wn_s[tid + 512] = g_wn1[tid + 512];
    __syncthreads();

    // build A fragments: slot s=tid -> kk=s>>6, mt=(s>>5)&1, lane=s&31
    {
        int s_  = tid;
        int kk  = s_ >> 6, mt = (s_ >> 5) & 1, ln = s_ & 31;
        int gg = ln >> 2, qq = ln & 3;
        int rr = mt * 16 + gg, k0 = kk * 8 + qq;
        float a0 = z_s[rr * 64 + k0];
        float a1 = z_s[(rr + 8) * 64 + k0];
        float a2 = z_s[rr * 64 + k0 + 4];
        float a3 = z_s[(rr + 8) * 64 + k0 + 4];
        uint32_t h0 = tf32_rna(a0), h1 = tf32_rna(a1),
                 h2 = tf32_rna(a2), h3 = tf32_rna(a3);
        float4 hv, lv;
        hv.x = __uint_as_float(h0); hv.y = __uint_as_float(h1);
        hv.z = __uint_as_float(h2); hv.w = __uint_as_float(h3);
        lv.x = __uint_as_float(tf32_rna(a0 - hv.x));
        lv.y = __uint_as_float(tf32_rna(a1 - hv.y));
        lv.z = __uint_as_float(tf32_rna(a2 - hv.z));
        lv.w = __uint_as_float(tf32_rna(a3 - hv.w));
        ((float4*)ahi_s)[s_] = hv;
        ((float4*)alo_s)[s_] = lv;
    }
    if (tid < 32) {
        float s = 0.f;
        const float* zr = z_s + tid * 64;
#pragma unroll 16
        for (int k = 0; k < 64; k++) { float v = zr[k]; s += v * v; }
        zn2_s[tid] = s;
    }
    __syncthreads();

    // ---- GEMM: acc[mt][nt][4] ----
    float acc[2][8][4];
#pragma unroll
    for (int mt = 0; mt < 2; mt++)
#pragma unroll
        for (int nt = 0; nt < 8; nt++)
#pragma unroll
            for (int r = 0; r < 4; r++) acc[mt][nt][r] = 0.f;

    const float4* bbase = (const float4*)g_bfrag + (size_t)(wid * 8 * 8) * 32 + lane;

#pragma unroll 1
    for (int kk = 0; kk < 8; kk++) {
        uint32_t ah[2][4], al[2][4];
#pragma unroll
        for (int mt = 0; mt < 2; mt++) {
            float4 h = ((const float4*)ahi_s)[(kk * 2 + mt) * 32 + lane];
            float4 l = ((const float4*)alo_s)[(kk * 2 + mt) * 32 + lane];
            ah[mt][0] = __float_as_uint(h.x); ah[mt][1] = __float_as_uint(h.y);
            ah[mt][2] = __float_as_uint(h.z); ah[mt][3] = __float_as_uint(h.w);
            al[mt][0] = __float_as_uint(l.x); al[mt][1] = __float_as_uint(l.y);
            al[mt][2] = __float_as_uint(l.z); al[mt][3] = __float_as_uint(l.w);
        }
        float4 bf = __ldg(bbase + kk * 32);
#pragma unroll
        for (int nt = 0; nt < 8; nt++) {
            float4 bc = bf;
            if (nt < 7) bf = __ldg(bbase + (nt + 1) * 256 + kk * 32);
            uint32_t bh0 = __float_as_uint(bc.x), bh1 = __float_as_uint(bc.y);
            uint32_t bl0 = __float_as_uint(bc.z), bl1 = __float_as_uint(bc.w);
#pragma unroll
            for (int mt = 0; mt < 2; mt++) {
                mma_tf32(acc[mt][nt], ah[mt], bh0, bh1);  // hi*hi
                mma_tf32(acc[mt][nt], ah[mt], bl0, bl1);  // hi*lo
                mma_tf32(acc[mt][nt], al[mt], bh0, bh1);  // lo*hi
            }
        }
    }

    // ---- epilogue: S = acc + zn2 + wn1 ; q_un = rcp(S); rowsum + argmax ----
    float rs[4] = {0.f, 0.f, 0.f, 0.f};
    unsigned long long key[4] = {0ull, 0ull, 0ull, 0ull};
    const int wc0 = wid * 64;

#pragma unroll
    for (int mt = 0; mt < 2; mt++) {
#pragma unroll
        for (int h = 0; h < 2; h++) {
            int rloc = mt * 16 + g + h * 8;
            float zn = zn2_s[rloc];
#pragma unroll
            for (int nt = 0; nt < 8; nt++) {
#pragma unroll
                for (int p = 0; p < 2; p++) {
                    int c  = wc0 + nt * 8 + tq * 2 + p;
                    float S = acc[mt][nt][h * 2 + p] + zn + wn_s[c];
                    float qv = rcpf(S);
                    acc[mt][nt][h * 2 + p] = qv;
                    rs[mt * 2 + h] += qv;
                    unsigned long long k =
                        ((unsigned long long)ordered_u32(S) << 32) |
                        (unsigned long long)(0xFFFFFFFFu - (unsigned int)c);
                    if (k > key[mt * 2 + h]) key[mt * 2 + h] = k;
                }
            }
        }
    }
    // quad reduce (lanes sharing g)
#pragma unroll
    for (int m = 1; m <= 2; m <<= 1) {
#pragma unroll
        for (int r = 0; r < 4; r++) {
            rs[r] += __shfl_xor_sync(0xFFFFFFFFu, rs[r], m);
            unsigned long long o = __shfl_xor_sync(0xFFFFFFFFu, key[r], m);
            if (o > key[r]) key[r] = o;
        }
    }
    if (tq == 0) {
#pragma unroll
        for (int r = 0; r < 4; r++) {
            int rloc = (r >> 1) * 16 + g + (r & 1) * 8;
            rs_p[wid][rloc]  = rs[r];
            key_p[wid][rloc] = key[r];
        }
    }
    __syncthreads();
    if (tid < 32) {
        float s = 0.f;
        unsigned long long bk = 0ull;
#pragma unroll
        for (int w = 0; w < NWARP; w++) {
            s += rs_p[w][tid];
            unsigned long long k = key_p[w][tid];
            if (k > bk) bk = k;
        }
        inv_s[tid] = 1.0f / s;
        bc_s[tid]  = (int)(0xFFFFFFFFu - (unsigned int)(bk & 0xFFFFFFFFull));
    }
    __syncthreads();

    // ---- store normalized q ----
#pragma unroll
    for (int mt = 0; mt < 2; mt++) {
#pragma unroll
        for (int h = 0; h < 2; h++) {
            int rloc = mt * 16 + g + h * 8;
            float inv = inv_s[rloc];
            float* base = q_out + (size_t)(r0 + rloc) * 1024 + wc0 + tq * 2;
#pragma unroll
            for (int nt = 0; nt < 8; nt++) {
                float2 v;
                v.x = acc[mt][nt][h * 2 + 0] * inv;
                v.y = acc[mt][nt][h * 2 + 1] * inv;
                *(float2*)(base + nt * 8) = v;
            }
        }
    }

    // ---- gather z_q, store, loss partial ----
    float lp = 0.f;
    {
        int rr = tid >> 4, j4 = tid & 15;
        int cbest = bc_s[rr];
        float4 e  = ((const float4*)(cb + (size_t)cbest * 64))[j4];
        float4 zv = ((const float4*)z_s)[rr * 16 + j4];
        ((float4*)(zq_out + (size_t)(r0 + rr) * 64))[j4] = e;
        float dx = e.x - zv.x, dy = e.y - zv.y,
              dz = e.z - zv.z, dw = e.w - zv.w;
        lp = dx * dx + dy * dy + dz * dz + dw * dw;
    }
    float* red = &rs_p[0][0];   // 512 floats
    red[tid] = lp;
    __syncthreads();
#pragma unroll
    for (int s = 256; s > 0; s >>= 1) {
        if (tid < s) red[tid] += red[tid + s];
        __syncthreads();
    }
    if (tid == 0) atomicAdd(&g_loss, (double)red[0]);
}

__global__ void vq_finalize(float* __restrict__ loss_out) {
    loss_out[0] = (float)(1.25 * g_loss / (65536.0 * 64.0));
}

extern "C" void kernel_launch(void* const* d_in, const int* in_sizes, int n_in,
                              void* d_out, int out_size) {
    (void)in_sizes; (void)n_in; (void)out_size;
    const float* z  = (const float*)d_in[0];
    const float* cb = (const float*)d_in[1];
    float* out      = (float*)d_out;
    float* q_out    = out;
    float* zq_out   = out + (size_t)65536 * 1024;
    float* loss_out = zq_out + (size_t)65536 * 64;

    vq_norms<<<8, 128>>>(cb);
    vq_bfrag<<<128, 256>>>(cb);
    vq_main<<<65536 / BM, THREADS>>>(z, cb, q_out, zq_out);
    vq_finalize<<<1, 1>>>(loss_out);
}